// round 7
// baseline (speedup 1.0000x reference)
#include <cuda_runtime.h>
#include <cstdint>

// Problem constants (fixed by setup_inputs)
#define BB 8192
#define DD 128
#define SCALE (-10.0f)   // -1/TEMPERATURE
#define NEGBIG (-1e30f)

// -------- scratch (no allocations allowed) --------
__device__ float g_sq[BB];
__device__ float g_num[BB];
__device__ int   g_valid[BB];
__device__ int   g_labs[BB];
__device__ float g_part[128];
__device__ int   g_cnt[64];
__device__ int   g_off[64];
__device__ int   g_bucket[BB];

// ---------------- threefry2x32, key = (0, 42) ----------------
__device__ __forceinline__ unsigned rotl32(unsigned x, int d) {
    return (x << d) | (x >> (32 - d));
}
__device__ __forceinline__ void threefry2x32(unsigned c0, unsigned c1,
                                             unsigned& o0, unsigned& o1) {
    const unsigned k0 = 0u, k1 = 42u;
    const unsigned k2 = 0x1BD11BDAu ^ k0 ^ k1;
    unsigned x0 = c0 + k0, x1 = c1 + k1;
#define TFR(r) { x0 += x1; x1 = rotl32(x1, r); x1 ^= x0; }
    TFR(13) TFR(15) TFR(26) TFR(6)
    x0 += k1; x1 += k2 + 1u;
    TFR(17) TFR(29) TFR(16) TFR(24)
    x0 += k2; x1 += k0 + 2u;
    TFR(13) TFR(15) TFR(26) TFR(6)
    x0 += k0; x1 += k1 + 3u;
    TFR(17) TFR(29) TFR(16) TFR(24)
    x0 += k1; x1 += k2 + 4u;
    TFR(13) TFR(15) TFR(26) TFR(6)
    x0 += k2; x1 += k0 + 5u;
#undef TFR
    o0 = x0; o1 = x1;
}

__device__ __forceinline__ unsigned jax_bits(unsigned long long idx) {
    // threefry_partitionable: msg = (hi32, lo32), draw = o0 ^ o1
    unsigned o0, o1;
    threefry2x32((unsigned)(idx >> 32), (unsigned)idx, o0, o1);
    return o0 ^ o1;
}

// ---- kernel 0: fused setup: dtype detect + convert + hist + scan + scatter ----
__global__ void setup_kernel(const unsigned* __restrict__ labels_raw) {
    __shared__ int s_is64;
    __shared__ int s_cnt[64], s_off[64], s_fill[64];
    const int tid = threadIdx.x;             // 1024 threads
    if (tid == 0) s_is64 = 1;
    if (tid < 64) { s_cnt[tid] = 0; s_fill[tid] = 0; }
    __syncthreads();
    // int64 labels in [0,64) have every odd 32-bit word == 0 (little-endian)
    if (tid < 128 && labels_raw[2 * tid + 1] != 0u) atomicExch(&s_is64, 0);
    __syncthreads();
    const int is64 = s_is64;
    int l[8];
    #pragma unroll
    for (int q = 0; q < 8; q++) {
        int i = tid + q * 1024;
        int lab = (int)labels_raw[is64 ? 2 * i : i] & 63;
        l[q] = lab;
        g_labs[i] = lab;
        atomicAdd(&s_cnt[lab], 1);
    }
    __syncthreads();
    if (tid == 0) {
        int o = 0;
        for (int k = 0; k < 64; k++) {
            s_off[k] = o; g_off[k] = o; g_cnt[k] = s_cnt[k]; o += s_cnt[k];
        }
    }
    __syncthreads();
    #pragma unroll
    for (int q = 0; q < 8; q++) {
        int i = tid + q * 1024;
        int p = atomicAdd(&s_fill[l[q]], 1);
        g_bucket[s_off[l[q]] + p] = i;
    }
}

// ---------------- kernel 1: row squared norms ----------------
__global__ void sq_kernel(const float* __restrict__ emb) {
    int wid  = (blockIdx.x * blockDim.x + threadIdx.x) >> 5;
    int lane = threadIdx.x & 31;
    if (wid >= BB) return;
    float4 v = ((const float4*)(emb + (size_t)wid * DD))[lane];
    float d = v.x * v.x + v.y * v.y + v.z * v.z + v.w * v.w;
    #pragma unroll
    for (int off = 16; off; off >>= 1) d += __shfl_xor_sync(0xffffffffu, d, off);
    if (lane == 0) g_sq[wid] = d;
}

// ---- kernel 2: gumbel-argmax positive over bucket, numerator, validity ----
__global__ void select_kernel(const float* __restrict__ emb) {
    int wid  = (blockIdx.x * blockDim.x + threadIdx.x) >> 5;
    int lane = threadIdx.x & 31;
    if (wid >= BB) return;
    const int i = wid;
    int labi = g_labs[i];
    int boff = g_off[labi], n = g_cnt[labi];
    unsigned long long best = 0ull;  // ((bits>>9)<<32) | (0xFFFFFFFF - j); 0 == none
    for (int p = lane; p < n; p += 32) {
        int j = g_bucket[boff + p];
        if (j != i) {
            unsigned long long idx = (unsigned long long)i * BB + (unsigned)j;
            unsigned bits = jax_bits(idx);
            unsigned long long key =
                ((unsigned long long)(bits >> 9) << 32) | (0xFFFFFFFFu - (unsigned)j);
            if (key > best) best = key;
        }
    }
    #pragma unroll
    for (int off = 16; off; off >>= 1) {
        unsigned long long o = __shfl_xor_sync(0xffffffffu, best, off);
        if (o > best) best = o;
    }
    int jbest = best ? (int)(0xFFFFFFFFu - (unsigned)(best & 0xFFFFFFFFull)) : -1;
    float nm = 0.f;
    if (jbest >= 0) {
        float4 av = ((const float4*)(emb + (size_t)i * DD))[lane];
        float4 bv = ((const float4*)(emb + (size_t)jbest * DD))[lane];
        float d = av.x * bv.x + av.y * bv.y + av.z * bv.z + av.w * bv.w;
        #pragma unroll
        for (int off = 16; off; off >>= 1) d += __shfl_xor_sync(0xffffffffu, d, off);
        float d2 = fmaxf(g_sq[i] + g_sq[jbest] - 2.f * d, 0.f);
        nm = SCALE * d2;
    }
    if (lane == 0) {
        g_num[i]   = nm;
        g_valid[i] = (jbest >= 0 && n < BB) ? 1 : 0;
    }
}

// ---- kernel 3: bf16x3 compensated mma.sync GEMM + masked online logsumexp ----
// 128 blocks x BM=64 rows. 8 warps: wm=wid>>1 (4 in M, 16 rows each),
// wn=wid&1 (2 in N, 64 cols each of the BN=128 tile).
// m16n8k16 bf16; dot = Ahi*Bhi + Ahi*Blo + Alo*Bhi (error ~2^-17 relative).
#define BM 64
#define BN 128
#define LDB 68    // B row stride in uint32 (bf16 pairs): bank = (4g+t), conflict-free
#define NT 256

__device__ __forceinline__ unsigned pack2bf(float lo, float hi) {
    unsigned r;
    asm("cvt.rn.bf16x2.f32 %0, %1, %2;" : "=r"(r) : "f"(hi), "f"(lo));
    return r;
}
__device__ __forceinline__ float bf_lo_f(unsigned p) { return __uint_as_float(p << 16); }
__device__ __forceinline__ float bf_hi_f(unsigned p) { return __uint_as_float(p & 0xffff0000u); }

#define MMA_BF16(ACC, A, B0, B1)                                            \
    asm volatile(                                                           \
        "mma.sync.aligned.m16n8k16.row.col.f32.bf16.bf16.f32 "              \
        "{%0,%1,%2,%3}, {%4,%5,%6,%7}, {%8,%9}, {%0,%1,%2,%3};\n"           \
        : "+f"(ACC[0]), "+f"(ACC[1]), "+f"(ACC[2]), "+f"(ACC[3])            \
        : "r"(A[0]), "r"(A[1]), "r"(A[2]), "r"(A[3]), "r"(B0), "r"(B1))

__global__ void __launch_bounds__(NT, 1)
main_kernel(const float* __restrict__ emb) {
    extern __shared__ char smem[];
    unsigned* Bhi  = (unsigned*)smem;                       // [128][68] packed bf16 pairs
    unsigned* Blo  = Bhi + BN * LDB;                        // [128][68]
    float*    Sq   = (float*)(Blo + BN * LDB);              // [128]
    int*      Ls   = (int*)(Sq + BN);                       // [128]
    float*    red_m = (float*)(Ls + BN);                    // [64]
    float*    red_s = red_m + 64;                           // [64]
    float*    wsum  = red_s + 64;                           // [8]
    float*    Astage = (float*)smem;                        // alias (prologue only): [64][132]

    const int tid  = threadIdx.x;
    const int wid  = tid >> 5;
    const int lane = tid & 31;
    const int wm   = wid >> 1;             // 0..3
    const int wn   = wid & 1;              // 0..1
    const int g    = lane >> 2;            // groupID 0..7
    const int t    = lane & 3;             // tid-in-group 0..3
    const int i0   = blockIdx.x * BM;
    const unsigned qmask = 0xFu << (lane & 28);

    // ---- prologue: stage A tile (fp32) in smem, build hi/lo bf16 fragments ----
    for (int p = tid; p < BM * 32; p += NT) {
        int r = p >> 5, k4 = p & 31;
        ((float4*)(Astage + r * 132))[k4] =
            ((const float4*)(emb + (size_t)(i0 + r) * DD))[k4];
    }
    __syncthreads();
    unsigned ah[8][4], al[8][4];
    {
        const float* r0p = Astage + (16 * wm + g) * 132;
        const float* r1p = r0p + 8 * 132;
        #pragma unroll
        for (int ks = 0; ks < 8; ks++) {
            float x0 = r0p[16 * ks + 2 * t],     x1 = r0p[16 * ks + 2 * t + 1];
            float x2 = r0p[16 * ks + 2 * t + 8], x3 = r0p[16 * ks + 2 * t + 9];
            float y0 = r1p[16 * ks + 2 * t],     y1 = r1p[16 * ks + 2 * t + 1];
            float y2 = r1p[16 * ks + 2 * t + 8], y3 = r1p[16 * ks + 2 * t + 9];
            ah[ks][0] = pack2bf(x0, x1); ah[ks][1] = pack2bf(y0, y1);
            ah[ks][2] = pack2bf(x2, x3); ah[ks][3] = pack2bf(y2, y3);
            al[ks][0] = pack2bf(x0 - bf_lo_f(ah[ks][0]), x1 - bf_hi_f(ah[ks][0]));
            al[ks][1] = pack2bf(y0 - bf_lo_f(ah[ks][1]), y1 - bf_hi_f(ah[ks][1]));
            al[ks][2] = pack2bf(x2 - bf_lo_f(ah[ks][2]), x3 - bf_hi_f(ah[ks][2]));
            al[ks][3] = pack2bf(y2 - bf_lo_f(ah[ks][3]), y3 - bf_hi_f(ah[ks][3]));
        }
    }
    // per-lane row state: rows r0 = i0+16wm+g, r1 = r0+8 (replicated over quad)
    const int r0 = i0 + 16 * wm + g, r1 = r0 + 8;
    const float sqr[2] = { g_sq[r0], g_sq[r1] };
    const int   lab[2] = { g_labs[r0], g_labs[r1] };
    float m[2] = { NEGBIG, NEGBIG };
    float s[2] = { 0.f, 0.f };
    __syncthreads();

    const unsigned* pbh = Bhi + (64 * wn + g) * LDB + t;
    const unsigned* pbl = Blo + (64 * wn + g) * LDB + t;

    for (int c0 = 0; c0 < BB; c0 += BN) {
        // load + split B tile [n][k-pairs] (coalesced float4 -> hi/lo bf16x2)
        for (int p = tid; p < BN * 32; p += NT) {
            int n = p >> 5, k4 = p & 31;
            float4 v = ((const float4*)(emb + (size_t)(c0 + n) * DD))[k4];
            unsigned h0 = pack2bf(v.x, v.y), h1 = pack2bf(v.z, v.w);
            unsigned l0 = pack2bf(v.x - bf_lo_f(h0), v.y - bf_hi_f(h0));
            unsigned l1 = pack2bf(v.z - bf_lo_f(h1), v.w - bf_hi_f(h1));
            ((uint2*)(Bhi + n * LDB))[k4] = make_uint2(h0, h1);
            ((uint2*)(Blo + n * LDB))[k4] = make_uint2(l0, l1);
        }
        if (tid < BN) { Sq[tid] = g_sq[c0 + tid]; Ls[tid] = g_labs[c0 + tid]; }
        __syncthreads();

        float acc[8][4];
        #pragma unroll
        for (int nt = 0; nt < 8; nt++) {
            acc[nt][0] = 0.f; acc[nt][1] = 0.f; acc[nt][2] = 0.f; acc[nt][3] = 0.f;
        }

        #pragma unroll
        for (int ks = 0; ks < 8; ks++) {
            #pragma unroll
            for (int nt = 0; nt < 8; nt++) {
                int off = nt * (8 * LDB) + 8 * ks;
                unsigned bh0 = pbh[off], bh1 = pbh[off + 4];
                unsigned bl0 = pbl[off], bl1 = pbl[off + 4];
                MMA_BF16(acc[nt], ah[ks], bh0, bh1);
                MMA_BF16(acc[nt], ah[ks], bl0, bl1);
                MMA_BF16(acc[nt], al[ks], bh0, bh1);
            }
        }

        // ---- epilogue: masked sims + online logsumexp (quad-scoped) ----
        #pragma unroll
        for (int rs = 0; rs < 2; rs++) {
            float vals[16];
            float tmax = NEGBIG;
            #pragma unroll
            for (int nt = 0; nt < 8; nt++) {
                int cc = 64 * wn + nt * 8 + 2 * t;
                float2 sq2 = *(const float2*)(Sq + cc);
                int2   lb2 = *(const int2*)(Ls + cc);
                float d2a = fmaxf(sqr[rs] + sq2.x - 2.f * acc[nt][2 * rs],     0.f);
                float d2b = fmaxf(sqr[rs] + sq2.y - 2.f * acc[nt][2 * rs + 1], 0.f);
                float va = (lab[rs] != lb2.x) ? SCALE * d2a : NEGBIG;
                float vb = (lab[rs] != lb2.y) ? SCALE * d2b : NEGBIG;
                vals[2 * nt]     = va;
                vals[2 * nt + 1] = vb;
                tmax = fmaxf(tmax, fmaxf(va, vb));
            }
            tmax = fmaxf(tmax, __shfl_xor_sync(0xffffffffu, tmax, 1, 4));
            tmax = fmaxf(tmax, __shfl_xor_sync(0xffffffffu, tmax, 2, 4));
            if (tmax > m[rs]) { s[rs] *= __expf(m[rs] - tmax); m[rs] = tmax; }
            if (m[rs] > -9e29f && tmax >= m[rs] - 25.f) {  // quad-uniform
                float p = 0.f;
                #pragma unroll
                for (int q = 0; q < 16; q++)
                    if (vals[q] >= m[rs] - 25.f) p += __expf(vals[q] - m[rs]);
                p += __shfl_xor_sync(qmask, p, 1, 4);
                p += __shfl_xor_sync(qmask, p, 2, 4);
                s[rs] += p;
            }
        }
        __syncthreads();
    }

    // ---- merge the two wn halves per row, reduce block sum ----
    const int lr0 = 16 * wm + g, lr1 = lr0 + 8;
    if (wn == 0 && t == 0) {
        red_m[lr0] = m[0]; red_s[lr0] = s[0];
        red_m[lr1] = m[1]; red_s[lr1] = s[1];
    }
    __syncthreads();
    float local = 0.f;
    if (wn == 1 && t == 0) {
        #pragma unroll
        for (int rs = 0; rs < 2; rs++) {
            int lr = (rs == 0) ? lr0 : lr1;
            int rr = (rs == 0) ? r0  : r1;
            float mo = red_m[lr], so = red_s[lr];
            float M = fmaxf(m[rs], mo);
            if (M > -9e29f) {
                float S = 0.f;
                if (m[rs] > -9e29f) S += s[rs] * __expf(m[rs] - M);
                if (mo    > -9e29f) S += so    * __expf(mo    - M);
                if (g_valid[rr] && S > 0.f)
                    local += M + logf(S) - g_num[rr];
            }
        }
    }
    #pragma unroll
    for (int off = 16; off; off >>= 1)
        local += __shfl_xor_sync(0xffffffffu, local, off);
    if (lane == 0) wsum[wid] = local;
    __syncthreads();
    if (tid == 0) {
        float tt = 0.f;
        #pragma unroll
        for (int k = 0; k < 8; k++) tt += wsum[k];
        g_part[blockIdx.x] = tt;
    }
}

// ---------------- kernel 4: final reduce ----------------
__global__ void finish_kernel(float* __restrict__ out, int nparts) {
    __shared__ float sh[4];
    int tid = threadIdx.x;               // 128 threads
    float v = (tid < nparts) ? g_part[tid] : 0.f;
    #pragma unroll
    for (int off = 16; off; off >>= 1) v += __shfl_xor_sync(0xffffffffu, v, off);
    if ((tid & 31) == 0) sh[tid >> 5] = v;
    __syncthreads();
    if (tid == 0) {
        float tt = sh[0] + sh[1] + sh[2] + sh[3];
        out[0] = tt / (float)BB;
    }
}

// ---------------- launch ----------------
extern "C" void kernel_launch(void* const* d_in, const int* in_sizes, int n_in,
                              void* d_out, int out_size) {
    const float*    emb        = (const float*)d_in[0];
    const unsigned* labels_raw = (const unsigned*)d_in[1];
    float*          out        = (float*)d_out;

    setup_kernel<<<1, 1024>>>(labels_raw);
    sq_kernel<<<BB * 32 / 256, 256>>>(emb);
    select_kernel<<<BB * 32 / 256, 256>>>(emb);

    const int smem_bytes = (2 * BN * LDB) * 4 + BN * 4 + BN * 4 + (64 + 64 + 8) * 4;
    cudaFuncSetAttribute(main_kernel, cudaFuncAttributeMaxDynamicSharedMemorySize,
                         smem_bytes);
    main_kernel<<<BB / BM, NT, smem_bytes>>>(emb);

    finish_kernel<<<1, 128>>>(out, BB / BM);
}

// round 8
// speedup vs baseline: 1.0726x; 1.0726x over previous
#include <cuda_runtime.h>
#include <cstdint>

// Problem constants (fixed by setup_inputs)
#define BB 8192
#define DD 128
#define SCALE (-10.0f)   // -1/TEMPERATURE
#define NEGBIG (-1e30f)

// -------- scratch (no allocations allowed) --------
__device__ float g_sq[BB];
__device__ float g_num[BB];
__device__ int   g_valid[BB];
__device__ int   g_labs[BB];
__device__ float g_part[256];
__device__ int   g_cnt[64];
__device__ int   g_off[64];
__device__ int   g_bucket[BB];

// ---------------- threefry2x32, key = (0, 42) ----------------
__device__ __forceinline__ unsigned rotl32(unsigned x, int d) {
    return (x << d) | (x >> (32 - d));
}
__device__ __forceinline__ void threefry2x32(unsigned c0, unsigned c1,
                                             unsigned& o0, unsigned& o1) {
    const unsigned k0 = 0u, k1 = 42u;
    const unsigned k2 = 0x1BD11BDAu ^ k0 ^ k1;
    unsigned x0 = c0 + k0, x1 = c1 + k1;
#define TFR(r) { x0 += x1; x1 = rotl32(x1, r); x1 ^= x0; }
    TFR(13) TFR(15) TFR(26) TFR(6)
    x0 += k1; x1 += k2 + 1u;
    TFR(17) TFR(29) TFR(16) TFR(24)
    x0 += k2; x1 += k0 + 2u;
    TFR(13) TFR(15) TFR(26) TFR(6)
    x0 += k0; x1 += k1 + 3u;
    TFR(17) TFR(29) TFR(16) TFR(24)
    x0 += k1; x1 += k2 + 4u;
    TFR(13) TFR(15) TFR(26) TFR(6)
    x0 += k2; x1 += k0 + 5u;
#undef TFR
    o0 = x0; o1 = x1;
}

__device__ __forceinline__ unsigned jax_bits(unsigned long long idx) {
    // threefry_partitionable: msg = (hi32, lo32), draw = o0 ^ o1
    unsigned o0, o1;
    threefry2x32((unsigned)(idx >> 32), (unsigned)idx, o0, o1);
    return o0 ^ o1;
}

// ---- kernel 0: fused setup: dtype detect + convert + hist + scan + scatter ----
__global__ void setup_kernel(const unsigned* __restrict__ labels_raw) {
    __shared__ int s_is64;
    __shared__ int s_cnt[64], s_off[64], s_fill[64];
    const int tid = threadIdx.x;             // 1024 threads
    if (tid == 0) s_is64 = 1;
    if (tid < 64) { s_cnt[tid] = 0; s_fill[tid] = 0; }
    __syncthreads();
    // int64 labels in [0,64) have every odd 32-bit word == 0 (little-endian)
    if (tid < 128 && labels_raw[2 * tid + 1] != 0u) atomicExch(&s_is64, 0);
    __syncthreads();
    const int is64 = s_is64;
    int l[8];
    #pragma unroll
    for (int q = 0; q < 8; q++) {
        int i = tid + q * 1024;
        int lab = (int)labels_raw[is64 ? 2 * i : i] & 63;
        l[q] = lab;
        g_labs[i] = lab;
        atomicAdd(&s_cnt[lab], 1);
    }
    __syncthreads();
    if (tid == 0) {
        int o = 0;
        for (int k = 0; k < 64; k++) {
            s_off[k] = o; g_off[k] = o; g_cnt[k] = s_cnt[k]; o += s_cnt[k];
        }
    }
    __syncthreads();
    #pragma unroll
    for (int q = 0; q < 8; q++) {
        int i = tid + q * 1024;
        int p = atomicAdd(&s_fill[l[q]], 1);
        g_bucket[s_off[l[q]] + p] = i;
    }
}

// ---------------- kernel 1: row squared norms ----------------
__global__ void sq_kernel(const float* __restrict__ emb) {
    int wid  = (blockIdx.x * blockDim.x + threadIdx.x) >> 5;
    int lane = threadIdx.x & 31;
    if (wid >= BB) return;
    float4 v = ((const float4*)(emb + (size_t)wid * DD))[lane];
    float d = v.x * v.x + v.y * v.y + v.z * v.z + v.w * v.w;
    #pragma unroll
    for (int off = 16; off; off >>= 1) d += __shfl_xor_sync(0xffffffffu, d, off);
    if (lane == 0) g_sq[wid] = d;
}

// ---- kernel 2: gumbel-argmax positive over bucket, numerator, validity ----
__global__ void select_kernel(const float* __restrict__ emb) {
    int wid  = (blockIdx.x * blockDim.x + threadIdx.x) >> 5;
    int lane = threadIdx.x & 31;
    if (wid >= BB) return;
    const int i = wid;
    int labi = g_labs[i];
    int boff = g_off[labi], n = g_cnt[labi];
    unsigned long long best = 0ull;  // ((bits>>9)<<32) | (0xFFFFFFFF - j); 0 == none
    for (int p = lane; p < n; p += 32) {
        int j = g_bucket[boff + p];
        if (j != i) {
            unsigned long long idx = (unsigned long long)i * BB + (unsigned)j;
            unsigned bits = jax_bits(idx);
            unsigned long long key =
                ((unsigned long long)(bits >> 9) << 32) | (0xFFFFFFFFu - (unsigned)j);
            if (key > best) best = key;
        }
    }
    #pragma unroll
    for (int off = 16; off; off >>= 1) {
        unsigned long long o = __shfl_xor_sync(0xffffffffu, best, off);
        if (o > best) best = o;
    }
    int jbest = best ? (int)(0xFFFFFFFFu - (unsigned)(best & 0xFFFFFFFFull)) : -1;
    float nm = 0.f;
    if (jbest >= 0) {
        float4 av = ((const float4*)(emb + (size_t)i * DD))[lane];
        float4 bv = ((const float4*)(emb + (size_t)jbest * DD))[lane];
        float d = av.x * bv.x + av.y * bv.y + av.z * bv.z + av.w * bv.w;
        #pragma unroll
        for (int off = 16; off; off >>= 1) d += __shfl_xor_sync(0xffffffffu, d, off);
        float d2 = fmaxf(g_sq[i] + g_sq[jbest] - 2.f * d, 0.f);
        nm = SCALE * d2;
    }
    if (lane == 0) {
        g_num[i]   = nm;
        g_valid[i] = (jbest >= 0 && n < BB) ? 1 : 0;
    }
}

// ---- kernel 3: bf16x3 compensated mma.sync GEMM + masked online logsumexp ----
// 256 blocks x BM=32 rows, 2 CTAs/SM (regs capped at 128). 8 warps:
// wm=wid>>2 (2 in M, 16 rows each), wn=wid&3 (4 in N, 32 cols of BN=128 tile).
// m16n8k16 bf16; dot = Ahi*Bhi + Ahi*Blo + Alo*Bhi (error ~2^-17 relative).
#define BM 32
#define BN 128
#define LDB 68    // B row stride in uint32 (bf16 pairs): bank = 4g+t+8ks, conflict-free
#define NT 256

__device__ __forceinline__ unsigned pack2bf(float lo, float hi) {
    unsigned r;
    asm("cvt.rn.bf16x2.f32 %0, %1, %2;" : "=r"(r) : "f"(hi), "f"(lo));
    return r;
}
__device__ __forceinline__ float bf_lo_f(unsigned p) { return __uint_as_float(p << 16); }
__device__ __forceinline__ float bf_hi_f(unsigned p) { return __uint_as_float(p & 0xffff0000u); }

#define MMA_BF16(ACC, A, B0, B1)                                            \
    asm volatile(                                                           \
        "mma.sync.aligned.m16n8k16.row.col.f32.bf16.bf16.f32 "              \
        "{%0,%1,%2,%3}, {%4,%5,%6,%7}, {%8,%9}, {%0,%1,%2,%3};\n"           \
        : "+f"(ACC[0]), "+f"(ACC[1]), "+f"(ACC[2]), "+f"(ACC[3])            \
        : "r"(A[0]), "r"(A[1]), "r"(A[2]), "r"(A[3]), "r"(B0), "r"(B1))

__global__ void __launch_bounds__(NT, 2)
main_kernel(const float* __restrict__ emb) {
    extern __shared__ char smem[];
    unsigned* Bhi   = (unsigned*)smem;                      // [128][68] packed bf16 pairs
    unsigned* Blo   = Bhi + BN * LDB;                       // [128][68]
    float*    Sq    = (float*)(Blo + BN * LDB);             // [128]
    int*      Ls    = (int*)(Sq + BN);                      // [128]
    float*    red_m = (float*)(Ls + BN);                    // [4][32]
    float*    red_s = red_m + 4 * 32;                       // [4][32]
    float*    wsum  = red_s + 4 * 32;                       // [8]
    float*    Astage = (float*)smem;                        // alias (prologue): [32][132]

    const int tid  = threadIdx.x;
    const int wid  = tid >> 5;
    const int lane = tid & 31;
    const int wm   = wid >> 2;             // 0..1
    const int wn   = wid & 3;              // 0..3
    const int g    = lane >> 2;            // groupID 0..7
    const int t    = lane & 3;             // tid-in-group 0..3
    const int i0   = blockIdx.x * BM;
    const unsigned qmask = 0xFu << (lane & 28);

    // ---- prologue: stage A tile (fp32) in smem, build hi/lo bf16 fragments ----
    for (int p = tid; p < BM * 32; p += NT) {
        int r = p >> 5, k4 = p & 31;
        ((float4*)(Astage + r * 132))[k4] =
            ((const float4*)(emb + (size_t)(i0 + r) * DD))[k4];
    }
    __syncthreads();
    unsigned ah[8][4], al[8][4];
    {
        const float* r0p = Astage + (16 * wm + g) * 132;
        const float* r1p = r0p + 8 * 132;
        #pragma unroll
        for (int ks = 0; ks < 8; ks++) {
            float x0 = r0p[16 * ks + 2 * t],     x1 = r0p[16 * ks + 2 * t + 1];
            float x2 = r0p[16 * ks + 2 * t + 8], x3 = r0p[16 * ks + 2 * t + 9];
            float y0 = r1p[16 * ks + 2 * t],     y1 = r1p[16 * ks + 2 * t + 1];
            float y2 = r1p[16 * ks + 2 * t + 8], y3 = r1p[16 * ks + 2 * t + 9];
            ah[ks][0] = pack2bf(x0, x1); ah[ks][1] = pack2bf(y0, y1);
            ah[ks][2] = pack2bf(x2, x3); ah[ks][3] = pack2bf(y2, y3);
            al[ks][0] = pack2bf(x0 - bf_lo_f(ah[ks][0]), x1 - bf_hi_f(ah[ks][0]));
            al[ks][1] = pack2bf(y0 - bf_lo_f(ah[ks][1]), y1 - bf_hi_f(ah[ks][1]));
            al[ks][2] = pack2bf(x2 - bf_lo_f(ah[ks][2]), x3 - bf_hi_f(ah[ks][2]));
            al[ks][3] = pack2bf(y2 - bf_lo_f(ah[ks][3]), y3 - bf_hi_f(ah[ks][3]));
        }
    }
    // per-lane row state: rows r0 = i0+16wm+g, r1 = r0+8 (replicated over quad)
    const int r0 = i0 + 16 * wm + g, r1 = r0 + 8;
    const float sqr[2] = { g_sq[r0], g_sq[r1] };
    const int   lab[2] = { g_labs[r0], g_labs[r1] };
    float m[2] = { NEGBIG, NEGBIG };
    float s[2] = { 0.f, 0.f };
    __syncthreads();

    const unsigned* pbh = Bhi + (32 * wn + g) * LDB + t;
    const unsigned* pbl = Blo + (32 * wn + g) * LDB + t;

    for (int c0 = 0; c0 < BB; c0 += BN) {
        // load + split B tile [n][k-pairs] (coalesced float4 -> hi/lo bf16x2)
        for (int p = tid; p < BN * 32; p += NT) {
            int n = p >> 5, k4 = p & 31;
            float4 v = ((const float4*)(emb + (size_t)(c0 + n) * DD))[k4];
            unsigned h0 = pack2bf(v.x, v.y), h1 = pack2bf(v.z, v.w);
            unsigned l0 = pack2bf(v.x - bf_lo_f(h0), v.y - bf_hi_f(h0));
            unsigned l1 = pack2bf(v.z - bf_lo_f(h1), v.w - bf_hi_f(h1));
            ((uint2*)(Bhi + n * LDB))[k4] = make_uint2(h0, h1);
            ((uint2*)(Blo + n * LDB))[k4] = make_uint2(l0, l1);
        }
        if (tid < BN) { Sq[tid] = g_sq[c0 + tid]; Ls[tid] = g_labs[c0 + tid]; }
        __syncthreads();

        float acc[4][4];
        #pragma unroll
        for (int nt = 0; nt < 4; nt++) {
            acc[nt][0] = 0.f; acc[nt][1] = 0.f; acc[nt][2] = 0.f; acc[nt][3] = 0.f;
        }

        #pragma unroll
        for (int ks = 0; ks < 8; ks++) {
            #pragma unroll
            for (int nt = 0; nt < 4; nt++) {
                int off = nt * (8 * LDB) + 8 * ks;
                unsigned bh0 = pbh[off], bh1 = pbh[off + 4];
                unsigned bl0 = pbl[off], bl1 = pbl[off + 4];
                MMA_BF16(acc[nt], ah[ks], bh0, bh1);
                MMA_BF16(acc[nt], ah[ks], bl0, bl1);
                MMA_BF16(acc[nt], al[ks], bh0, bh1);
            }
        }

        // ---- epilogue: masked sims + online logsumexp (quad-scoped) ----
        #pragma unroll
        for (int rs = 0; rs < 2; rs++) {
            float vals[8];
            float tmax = NEGBIG;
            #pragma unroll
            for (int nt = 0; nt < 4; nt++) {
                int cc = 32 * wn + nt * 8 + 2 * t;
                float2 sq2 = *(const float2*)(Sq + cc);
                int2   lb2 = *(const int2*)(Ls + cc);
                float d2a = fmaxf(sqr[rs] + sq2.x - 2.f * acc[nt][2 * rs],     0.f);
                float d2b = fmaxf(sqr[rs] + sq2.y - 2.f * acc[nt][2 * rs + 1], 0.f);
                float va = (lab[rs] != lb2.x) ? SCALE * d2a : NEGBIG;
                float vb = (lab[rs] != lb2.y) ? SCALE * d2b : NEGBIG;
                vals[2 * nt]     = va;
                vals[2 * nt + 1] = vb;
                tmax = fmaxf(tmax, fmaxf(va, vb));
            }
            tmax = fmaxf(tmax, __shfl_xor_sync(0xffffffffu, tmax, 1, 4));
            tmax = fmaxf(tmax, __shfl_xor_sync(0xffffffffu, tmax, 2, 4));
            if (tmax > m[rs]) { s[rs] *= __expf(m[rs] - tmax); m[rs] = tmax; }
            if (m[rs] > -9e29f && tmax >= m[rs] - 25.f) {  // quad-uniform
                float p = 0.f;
                #pragma unroll
                for (int q = 0; q < 8; q++)
                    if (vals[q] >= m[rs] - 25.f) p += __expf(vals[q] - m[rs]);
                p += __shfl_xor_sync(qmask, p, 1, 4);
                p += __shfl_xor_sync(qmask, p, 2, 4);
                s[rs] += p;
            }
        }
        __syncthreads();
    }

    // ---- merge the 4 wn parts per row (fixed order => deterministic) ----
    const int lr0 = 16 * wm + g, lr1 = lr0 + 8;
    if (t == 0) {
        red_m[wn * 32 + lr0] = m[0]; red_s[wn * 32 + lr0] = s[0];
        red_m[wn * 32 + lr1] = m[1]; red_s[wn * 32 + lr1] = s[1];
    }
    __syncthreads();
    float local = 0.f;
    if (wn == 0 && t == 0) {
        #pragma unroll
        for (int rs = 0; rs < 2; rs++) {
            int lr = (rs == 0) ? lr0 : lr1;
            int rr = (rs == 0) ? r0  : r1;
            float M = NEGBIG;
            #pragma unroll
            for (int w = 0; w < 4; w++) M = fmaxf(M, red_m[w * 32 + lr]);
            if (M > -9e29f) {
                float S = 0.f;
                #pragma unroll
                for (int w = 0; w < 4; w++) {
                    float mw = red_m[w * 32 + lr];
                    if (mw > -9e29f) S += red_s[w * 32 + lr] * __expf(mw - M);
                }
                if (g_valid[rr] && S > 0.f)
                    local += M + logf(S) - g_num[rr];
            }
        }
    }
    #pragma unroll
    for (int off = 16; off; off >>= 1)
        local += __shfl_xor_sync(0xffffffffu, local, off);
    if (lane == 0) wsum[wid] = local;
    __syncthreads();
    if (tid == 0) {
        float tt = 0.f;
        #pragma unroll
        for (int k = 0; k < 8; k++) tt += wsum[k];
        g_part[blockIdx.x] = tt;
    }
}

// ---------------- kernel 4: final reduce (256 partials) ----------------
__global__ void finish_kernel(float* __restrict__ out, int nparts) {
    __shared__ float sh[8];
    int tid = threadIdx.x;               // 256 threads
    float v = (tid < nparts) ? g_part[tid] : 0.f;
    #pragma unroll
    for (int off = 16; off; off >>= 1) v += __shfl_xor_sync(0xffffffffu, v, off);
    if ((tid & 31) == 0) sh[tid >> 5] = v;
    __syncthreads();
    if (tid == 0) {
        float tt = 0.f;
        #pragma unroll
        for (int k = 0; k < 8; k++) tt += sh[k];
        out[0] = tt / (float)BB;
    }
}

// ---------------- launch ----------------
extern "C" void kernel_launch(void* const* d_in, const int* in_sizes, int n_in,
                              void* d_out, int out_size) {
    const float*    emb        = (const float*)d_in[0];
    const unsigned* labels_raw = (const unsigned*)d_in[1];
    float*          out        = (float*)d_out;

    setup_kernel<<<1, 1024>>>(labels_raw);
    sq_kernel<<<BB * 32 / 256, 256>>>(emb);
    select_kernel<<<BB * 32 / 256, 256>>>(emb);

    const int smem_bytes = (2 * BN * LDB) * 4 + BN * 4 + BN * 4
                         + (4 * 32 + 4 * 32 + 8) * 4;
    cudaFuncSetAttribute(main_kernel, cudaFuncAttributeMaxDynamicSharedMemorySize,
                         smem_bytes);
    main_kernel<<<BB / BM, NT, smem_bytes>>>(emb);

    finish_kernel<<<1, 256>>>(out, BB / BM);
}